// round 10
// baseline (speedup 1.0000x reference)
#include <cuda_runtime.h>

#define Bc 256
#define Tc 4096

#define CH 32      // chunks over T
#define CL 128     // stored steps per chunk (CH*CL == Tc)
#define CW 64      // warmup steps (discarded)
#define NB 32      // batches per fused block
#define NG (Bc/NB) // batch groups = 8
#define CL2 (CL+2) // padded smem row (float2 units)
#define NTH 256    // warps 0-2 scan, warps 3-7 prefetch; all 8 combine

#define LOG2E 1.4426950408889634f
#define LN2   0.6931471805599453f

// emission probs, [b][t]-major
static __device__ __align__(16) float2 g_pe[Bc*Tc];

__device__ __forceinline__ float tanha(float x){ float y; asm("tanh.approx.f32 %0, %1;":"=f"(y):"f"(x)); return y; }
__device__ __forceinline__ float ex2a (float x){ float y; asm("ex2.approx.f32 %0, %1;" :"=f"(y):"f"(x)); return y; }
__device__ __forceinline__ float lg2a (float x){ float y; asm("lg2.approx.f32 %0, %1;" :"=f"(y):"f"(x)); return y; }
__device__ __forceinline__ float rcpa (float x){ float y; asm("rcp.approx.f32 %0, %1;" :"=f"(y):"f"(x)); return y; }
__device__ __forceinline__ void pref_l2(const void* p){ asm volatile("prefetch.global.L2 [%0];" :: "l"(p)); }

// ---------------------------------------------------------------------------
// Kernel 1: emitter -> g_pe. Fully coalesced.
// ---------------------------------------------------------------------------
__global__ void prep_kernel(const float* __restrict__ x,
                            const float* __restrict__ fc1_w, const float* __restrict__ fc1_b,
                            const float* __restrict__ fc2_w, const float* __restrict__ fc2_b)
{
    int j  = blockIdx.x*blockDim.x + threadIdx.x;
    int t0 = (j & (Tc/4 - 1)) << 2;
    int b  = j >> 10;

    float w1[8][3], bb1[8], w2a[8], w2b[8];
    #pragma unroll
    for (int e=0;e<8;e++){
        bb1[e] = fc1_b[e];
        #pragma unroll
        for (int d=0;d<3;d++) w1[e][d] = fc1_w[e*3+d];
        w2a[e] = fc2_w[e];
        w2b[e] = fc2_w[8+e];
    }
    float l0b = fc2_b[0], l1b = fc2_b[1];

    const float4* xv = (const float4*)(x + ((size_t)b*Tc + t0)*3);
    float4 v0 = xv[0], v1 = xv[1], v2 = xv[2];
    float xs[12] = {v0.x,v0.y,v0.z,v0.w, v1.x,v1.y,v1.z,v1.w, v2.x,v2.y,v2.z,v2.w};

    float4 peo[2];
    float2* pp = (float2*)peo;
    #pragma unroll
    for (int s=0;s<4;s++){
        float x0=xs[3*s], x1=xs[3*s+1], x2=xs[3*s+2];
        float l0=l0b, l1=l1b;
        #pragma unroll
        for (int e=0;e<8;e++){
            float te = tanha(fmaf(w1[e][2],x2, fmaf(w1[e][1],x1, fmaf(w1[e][0],x0, bb1[e]))));
            l0 = fmaf(w2a[e], te, l0);
            l1 = fmaf(w2b[e], te, l1);
        }
        float m = fmaxf(l0,l1);
        pp[s] = make_float2(ex2a((l0-m)*LOG2E), ex2a((l1-m)*LOG2E));
    }
    float4* po = (float4*)(g_pe + (size_t)b*Tc + t0);
    po[0] = peo[0]; po[1] = peo[1];
}

// ---------------------------------------------------------------------------
// Kernel 2: fused scans + combine. Grid = CH*NG = 256 blocks x 256 threads.
// Warp 0: GRU, warp 1: alpha, warp 2: beta -> smem tiles.
// Warps 3-7: L2-prefetch the block's Q tile during the scan phase.
// Then all 8 warps run the pair-vectorized combine epilogue.
// ---------------------------------------------------------------------------
__global__ void __launch_bounds__(NTH,2) fused_kernel(
                            const float* __restrict__ x,
                            const float* __restrict__ log_pi,
                            const float* __restrict__ log_A,
                            const float* __restrict__ w_ih,
                            const float* __restrict__ w_hh,
                            const float* __restrict__ b_ih,
                            const float* __restrict__ b_hh,
                            const float* __restrict__ Q_seq,
                            const float* __restrict__ Wg,
                            const float* __restrict__ by,
                            float* __restrict__ out)
{
    extern __shared__ float2 sh[];
    float2* sh_h  = sh;
    float2* sh_al = sh +     NB*CL2;
    float2* sh_be = sh + 2*NB*CL2;

    int c    = blockIdx.x >> 3;          // chunk
    int b0   = (blockIdx.x & (NG-1)) * NB;
    int tid  = threadIdx.x;
    int role = tid >> 5;
    int bl   = tid & (NB-1);
    int b    = b0 + bl;
    int t_store = c*CL;

    if (role == 0) {
        // ---------------- GRU ----------------
        float Wx[6][3], Bx[6];
        #pragma unroll
        for (int r=0;r<6;r++){
            float sc = (r<4) ? 0.5f : 1.0f;
            #pragma unroll
            for (int d=0;d<3;d++) Wx[r][d] = w_ih[r*3+d]*sc;
            Bx[r] = (r<4) ? 0.5f*(b_ih[r]+b_hh[r]) : b_ih[r];
        }
        float wh[6][2];
        #pragma unroll
        for (int r=0;r<6;r++){
            wh[r][0] = 0.5f*w_hh[r*2+0];
            wh[r][1] = 0.5f*w_hh[r*2+1];
        }
        float bn0 = 0.5f*b_hh[4], bn1 = 0.5f*b_hh[5];

        int t_beg = t_store - CW; if (t_beg < 0) t_beg = 0;
        int t_end = t_store + CL;

        const float* xrow = x + (size_t)b*Tc*3;
        float4 XA[3], XB[3], XC[3];
        {
            const float4* p0 = (const float4*)(xrow + t_beg*3);
            XA[0]=p0[0]; XA[1]=p0[1]; XA[2]=p0[2];
            const float4* p1 = (const float4*)(xrow + (t_beg+4)*3);
            XB[0]=p1[0]; XB[1]=p1[1]; XB[2]=p1[2];
            const float4* p2 = (const float4*)(xrow + (t_beg+8)*3);
            XC[0]=p2[0]; XC[1]=p2[1]; XC[2]=p2[2];
        }
        float h0=0.f, h1=0.f;
        float hq[8];
        for (int tg=t_beg; tg<t_end; tg+=4){
            float xs[12] = {XA[0].x,XA[0].y,XA[0].z,XA[0].w,
                            XA[1].x,XA[1].y,XA[1].z,XA[1].w,
                            XA[2].x,XA[2].y,XA[2].z,XA[2].w};
            XA[0]=XB[0]; XA[1]=XB[1]; XA[2]=XB[2];
            XB[0]=XC[0]; XB[1]=XC[1]; XB[2]=XC[2];
            {
                int gn = tg+12; if (gn > t_end-4) gn = t_end-4;
                const float4* p = (const float4*)(xrow + gn*3);
                XC[0]=p[0]; XC[1]=p[1]; XC[2]=p[2];
            }
            #pragma unroll
            for (int s=0;s<4;s++){
                float x0=xs[3*s], x1=xs[3*s+1], x2=xs[3*s+2];
                float xr0 = fmaf(Wx[0][2],x2, fmaf(Wx[0][1],x1, fmaf(Wx[0][0],x0, Bx[0])));
                float xr1 = fmaf(Wx[1][2],x2, fmaf(Wx[1][1],x1, fmaf(Wx[1][0],x0, Bx[1])));
                float xz0 = fmaf(Wx[2][2],x2, fmaf(Wx[2][1],x1, fmaf(Wx[2][0],x0, Bx[2])));
                float xz1 = fmaf(Wx[3][2],x2, fmaf(Wx[3][1],x1, fmaf(Wx[3][0],x0, Bx[3])));
                float xn0 = fmaf(Wx[4][2],x2, fmaf(Wx[4][1],x1, fmaf(Wx[4][0],x0, Bx[4])));
                float xn1 = fmaf(Wx[5][2],x2, fmaf(Wx[5][1],x1, fmaf(Wx[5][0],x0, Bx[5])));

                float ar0 = fmaf(wh[0][1],h1, fmaf(wh[0][0],h0, xr0));
                float ar1 = fmaf(wh[1][1],h1, fmaf(wh[1][0],h0, xr1));
                float az0 = fmaf(wh[2][1],h1, fmaf(wh[2][0],h0, xz0));
                float az1 = fmaf(wh[3][1],h1, fmaf(wh[3][0],h0, xz1));
                float hh0 = fmaf(wh[4][1],h1, fmaf(wh[4][0],h0, bn0));
                float hh1 = fmaf(wh[5][1],h1, fmaf(wh[5][0],h0, bn1));

                float tr0 = tanha(ar0), tr1 = tanha(ar1);
                float tz0 = tanha(az0), tz1 = tanha(az1);
                float c0 = xn0 + hh0, c1 = xn1 + hh1;
                float n0 = tanha(fmaf(tr0, hh0, c0));
                float n1 = tanha(fmaf(tr1, hh1, c1));
                float z0 = fmaf(tz0, 0.5f, 0.5f);
                float z1 = fmaf(tz1, 0.5f, 0.5f);
                float zh0 = z0*h0, zh1 = z1*h1;
                h0 = fmaf(1.f - z0, n0, zh0);
                h1 = fmaf(1.f - z1, n1, zh1);
                hq[2*s] = h0; hq[2*s+1] = h1;
            }
            if (tg >= t_store){
                float4* hv = (float4*)(sh_h + bl*CL2 + (tg - t_store));
                hv[0] = make_float4(hq[0],hq[1],hq[2],hq[3]);
                hv[1] = make_float4(hq[4],hq[5],hq[6],hq[7]);
            }
        }
    } else if (role == 1) {
        // ---------------- HMM forward (alpha) ----------------
        float e00 = __expf(log_A[0]), e01 = __expf(log_A[1]);
        float e10 = __expf(log_A[2]), e11 = __expf(log_A[3]);
        float P00 = e00/(e00+e01), P01 = e01/(e00+e01);
        float P10 = e10/(e10+e11), P11 = e11/(e10+e11);
        const float2* row = g_pe + (size_t)b*Tc;

        int t_end = t_store + CL;
        int t0    = (c==0) ? 0 : (t_store - CW);

        float4 PA[2], PB[2], PC[2];
        { const float4* p=(const float4*)(row+t0);    PA[0]=p[0]; PA[1]=p[1]; }
        { const float4* p=(const float4*)(row+t0+4);  PB[0]=p[0]; PB[1]=p[1]; }
        { const float4* p=(const float4*)(row+t0+8);  PC[0]=p[0]; PC[1]=p[1]; }

        float a0, a1;
        float ab[8];
        if (c == 0) {
            float ep0 = __expf(log_pi[0]), ep1 = __expf(log_pi[1]);
            float pi0 = ep0/(ep0+ep1), pi1 = ep1/(ep0+ep1);
            a0 = pi0*PA[0].x; a1 = pi1*PA[0].y;
            float r = rcpa(a0+a1); a0*=r; a1*=r;
        } else { a0 = 0.5f; a1 = 0.5f; }
        ab[0]=a0; ab[1]=a1;
        {
            float pex[3] = {PA[0].z, PA[1].x, PA[1].z};
            float pey[3] = {PA[0].w, PA[1].y, PA[1].w};
            #pragma unroll
            for (int s=0;s<3;s++){
                float u0 = (P00*a0 + P10*a1)*pex[s];
                float u1 = (P01*a0 + P11*a1)*pey[s];
                float r = rcpa(u0+u1);
                a0 = u0*r; a1 = u1*r;
                ab[2*s+2]=a0; ab[2*s+3]=a1;
            }
        }
        if (t0 == t_store){
            float4* av = (float4*)(sh_al + bl*CL2 + 0);
            av[0] = make_float4(ab[0],ab[1],ab[2],ab[3]);
            av[1] = make_float4(ab[4],ab[5],ab[6],ab[7]);
        }
        PA[0]=PB[0]; PA[1]=PB[1]; PB[0]=PC[0]; PB[1]=PC[1];
        { int gn=t0+12; if (gn>t_end-4) gn=t_end-4;
          const float4* p=(const float4*)(row+gn); PC[0]=p[0]; PC[1]=p[1]; }

        for (int tg=t0+4; tg<t_end; tg+=4){
            float pex[4] = {PA[0].x, PA[0].z, PA[1].x, PA[1].z};
            float pey[4] = {PA[0].y, PA[0].w, PA[1].y, PA[1].w};
            PA[0]=PB[0]; PA[1]=PB[1]; PB[0]=PC[0]; PB[1]=PC[1];
            { int gn=tg+12; if (gn>t_end-4) gn=t_end-4;
              const float4* p=(const float4*)(row+gn); PC[0]=p[0]; PC[1]=p[1]; }
            #pragma unroll
            for (int s=0;s<4;s++){
                float u0 = (P00*a0 + P10*a1)*pex[s];
                float u1 = (P01*a0 + P11*a1)*pey[s];
                float r = rcpa(u0+u1);
                a0 = u0*r; a1 = u1*r;
                ab[2*s]=a0; ab[2*s+1]=a1;
            }
            if (tg >= t_store){
                float4* av = (float4*)(sh_al + bl*CL2 + (tg - t_store));
                av[0] = make_float4(ab[0],ab[1],ab[2],ab[3]);
                av[1] = make_float4(ab[4],ab[5],ab[6],ab[7]);
            }
        }
    } else if (role == 2) {
        // ---------------- HMM backward (beta) ----------------
        float e00 = __expf(log_A[0]), e01 = __expf(log_A[1]);
        float e10 = __expf(log_A[2]), e11 = __expf(log_A[3]);
        float P00 = e00/(e00+e01), P01 = e01/(e00+e01);
        float P10 = e10/(e10+e11), P11 = e11/(e10+e11);
        const float2* row = g_pe + (size_t)b*Tc;

        int t_last = t_store + CL - 1;
        int t_hi   = t_last + CW; if (t_hi > Tc-1) t_hi = Tc-1;
        int gb_top = t_hi - 3;

        float4 PA[2], PB[2], PC[2];
        { const float4* p=(const float4*)(row+gb_top);   PA[0]=p[0]; PA[1]=p[1]; }
        { int g=gb_top-4; if (g<t_store) g=t_store;
          const float4* p=(const float4*)(row+g);        PB[0]=p[0]; PB[1]=p[1]; }
        { int g=gb_top-8; if (g<t_store) g=t_store;
          const float4* p=(const float4*)(row+g);        PC[0]=p[0]; PC[1]=p[1]; }

        float v0 = 0.5f, v1 = 0.5f;
        float vb[8];
        float2 carry;
        vb[6]=v0; vb[7]=v1;
        {
            float pex[3] = {PA[0].z, PA[1].x, PA[1].z};
            float pey[3] = {PA[0].w, PA[1].y, PA[1].w};
            #pragma unroll
            for (int s=2;s>=0;s--){
                float w0 = pex[s]*v0, w1 = pey[s]*v1;
                float n0 = P00*w0 + P01*w1;
                float n1 = P10*w0 + P11*w1;
                float r = rcpa(n0+n1);
                v0 = n0*r; v1 = n1*r;
                vb[2*s]=v0; vb[2*s+1]=v1;
            }
        }
        if (gb_top <= t_last-3){
            float4* bv = (float4*)(sh_be + bl*CL2 + (gb_top - t_store));
            bv[0] = make_float4(vb[0],vb[1],vb[2],vb[3]);
            bv[1] = make_float4(vb[4],vb[5],vb[6],vb[7]);
        }
        carry = make_float2(PA[0].x, PA[0].y);
        PA[0]=PB[0]; PA[1]=PB[1]; PB[0]=PC[0]; PB[1]=PC[1];
        { int gn=gb_top-12; if (gn<t_store) gn=t_store;
          const float4* p=(const float4*)(row+gn); PC[0]=p[0]; PC[1]=p[1]; }

        for (int gb=gb_top-4; gb>=t_store; gb-=4){
            float pex[4] = {carry.x, PA[0].z, PA[1].x, PA[1].z};
            float pey[4] = {carry.y, PA[0].w, PA[1].y, PA[1].w};
            carry = make_float2(PA[0].x, PA[0].y);
            PA[0]=PB[0]; PA[1]=PB[1]; PB[0]=PC[0]; PB[1]=PC[1];
            { int gn=gb-12; if (gn<t_store) gn=t_store;
              const float4* p=(const float4*)(row+gn); PC[0]=p[0]; PC[1]=p[1]; }
            {   // s = 3 uses pe[gb+4]
                float w0 = pex[0]*v0, w1 = pey[0]*v1;
                float n0 = P00*w0 + P01*w1;
                float n1 = P10*w0 + P11*w1;
                float r = rcpa(n0+n1);
                v0 = n0*r; v1 = n1*r;
                vb[6]=v0; vb[7]=v1;
            }
            #pragma unroll
            for (int s=2;s>=0;s--){
                float w0 = pex[s+1]*v0, w1 = pey[s+1]*v1;
                float n0 = P00*w0 + P01*w1;
                float n1 = P10*w0 + P11*w1;
                float r = rcpa(n0+n1);
                v0 = n0*r; v1 = n1*r;
                vb[2*s]=v0; vb[2*s+1]=v1;
            }
            if (gb <= t_last-3){
                float4* bv = (float4*)(sh_be + bl*CL2 + (gb - t_store));
                bv[0] = make_float4(vb[0],vb[1],vb[2],vb[3]);
                bv[1] = make_float4(vb[4],vb[5],vb[6],vb[7]);
            }
        }
    } else {
        // ---------------- roles 3-7: L2-prefetch the Q tile ----------------
        // Tile: NB rows, row kb at Q_seq + (b0+kb)*Tc*10 + t_store*10, 5120B each.
        // 1280 cache lines over 160 threads -> 8 prefetches per thread.
        const char* qbase = (const char*)Q_seq + ((size_t)b0*Tc + t_store)*40;
        int widx = tid - 96;                 // 0..159
        #pragma unroll
        for (int i=0;i<8;i++){
            int l  = widx + i*160;           // 0..1279
            int r  = l / 40;
            int cc = l - r*40;
            pref_l2(qbase + (size_t)r*(Tc*40) + cc*128);
        }
    }

    __syncthreads();

    // ---------------- combine epilogue: 2 elements (t, t+1) per thread ----
    float WgR[20];
    #pragma unroll
    for (int i=0;i<20;i++) WgR[i] = Wg[i];
    float by00=by[0], by01=by[1], by10=by[2], by11=by[3];

    #pragma unroll
    for (int it=0; it<(NB*CL/2)/NTH; ++it){
        int p  = tid + it*NTH;               // pair index
        int kb = p >> 6;                     // CL/2 = 64 pairs per row
        int tt = (p & 63) << 1;
        size_t j = (size_t)(b0+kb)*Tc + t_store + tt;   // even
        int si = kb*CL2 + tt;

        // Q for both elements: 80B, 16B-aligned
        const float4* qv = (const float4*)(Q_seq + j*10);
        float4 Q0 = qv[0], Q1 = qv[1], Q2 = qv[2], Q3 = qv[3], Q4 = qv[4];

        float4 alv = *(const float4*)(sh_al + si);
        float4 bev = *(const float4*)(sh_be + si);
        float4 hhv = *(const float4*)(sh_h  + si);

        float gA[5], gB[5];
        float lg0A,lg1A,lg0B,lg1B, d0A,d1A,lsA, d0B,d1B,lsB;

        #pragma unroll
        for (int e=0;e<2;e++){
            float alx = e? alv.z : alv.x,  aly = e? alv.w : alv.y;
            float bex = e? bev.z : bev.x,  bey = e? bev.w : bev.y;
            float hx  = e? hhv.z : hhv.x,  hy  = e? hhv.w : hhv.y;
            float* g  = e? gB : gA;

            float p0 = alx*bex, p1 = aly*bey;
            float s  = p0 + p1;
            float inv = rcpa(s);
            float gm0 = p0*inv, gm1 = p1*inv;
            float l2s = lg2a(s);
            float lg0 = (lg2a(p0) - l2s)*LN2;
            float lg1 = (lg2a(p1) - l2s)*LN2;

            float wh0[5], wh1[5];
            #pragma unroll
            for (int a=0;a<5;a++){
                wh0[a] = hx*WgR[a]    + hy*WgR[5+a];
                wh1[a] = hx*WgR[10+a] + hy*WgR[15+a];
            }
            float m0 = wh0[0], m1 = wh1[0];
            #pragma unroll
            for (int a=1;a<5;a++){ m0 = fmaxf(m0, wh0[a]); m1 = fmaxf(m1, wh1[a]); }
            float e0[5], e1[5], s0=0.f, s1=0.f;
            #pragma unroll
            for (int a=0;a<5;a++){
                e0[a] = ex2a((wh0[a]-m0)*LOG2E); s0 += e0[a];
                e1[a] = ex2a((wh1[a]-m1)*LOG2E); s1 += e1[a];
            }
            float i0 = rcpa(s0)*gm0, i1 = rcpa(s1)*gm1;
            #pragma unroll
            for (int a=0;a<5;a++) g[a] = e0[a]*i0 + e1[a]*i1;

            float q0,q1,q2,q3,q4,q5,q6,q7,q8,q9;
            if (!e){ q0=Q0.x;q1=Q0.y;q2=Q0.z;q3=Q0.w;q4=Q1.x;q5=Q1.y;q6=Q1.z;q7=Q1.w;q8=Q2.x;q9=Q2.y; }
            else   { q0=Q2.z;q1=Q2.w;q2=Q3.x;q3=Q3.y;q4=Q3.z;q5=Q3.w;q6=Q4.x;q7=Q4.y;q8=Q4.z;q9=Q4.w; }

            float V0 = gm0*by00 + gm1*by10;
            float V1 = gm0*by01 + gm1*by11;
            V0 = fmaf(g[0],q0, fmaf(g[1],q2, fmaf(g[2],q4, fmaf(g[3],q6, fmaf(g[4],q8, V0)))));
            V1 = fmaf(g[0],q1, fmaf(g[1],q3, fmaf(g[2],q5, fmaf(g[3],q7, fmaf(g[4],q9, V1)))));
            float mv = fmaxf(V0, V1);
            float d0 = V0-mv, d1 = V1-mv;
            float ls = lg2a(ex2a(d0*LOG2E) + ex2a(d1*LOG2E))*LN2;

            if (!e){ d0A=d0; d1A=d1; lsA=ls; lg0A=lg0; lg1A=lg1; }
            else   { d0B=d0; d1B=d1; lsB=ls; lg0B=lg0; lg1B=lg1; }
        }

        // pi_log: 16B-aligned STG.128
        *(float4*)(out + j*2) = make_float4(d0A-lsA, d1A-lsA, d0B-lsB, d1B-lsB);
        // g: 10 floats, 8B-aligned -> 5x STG.64
        float2* og = (float2*)(out + (size_t)Bc*Tc*2 + j*5);
        og[0] = make_float2(gA[0],gA[1]);
        og[1] = make_float2(gA[2],gA[3]);
        og[2] = make_float2(gA[4],gB[0]);
        og[3] = make_float2(gB[1],gB[2]);
        og[4] = make_float2(gB[3],gB[4]);
        // log_gamma: 16B-aligned STG.128
        *(float4*)(out + (size_t)Bc*Tc*7 + j*2) = make_float4(lg0A, lg1A, lg0B, lg1B);
    }
}

// ---------------------------------------------------------------------------
extern "C" void kernel_launch(void* const* d_in, const int* in_sizes, int n_in,
                              void* d_out, int out_size)
{
    const float* x      = (const float*)d_in[0];
    const float* Q_seq  = (const float*)d_in[1];
    const float* log_pi = (const float*)d_in[2];
    const float* log_A  = (const float*)d_in[3];
    const float* fc1_w  = (const float*)d_in[4];
    const float* fc1_b  = (const float*)d_in[5];
    const float* fc2_w  = (const float*)d_in[6];
    const float* fc2_b  = (const float*)d_in[7];
    const float* w_ih   = (const float*)d_in[8];
    const float* w_hh   = (const float*)d_in[9];
    const float* b_ih   = (const float*)d_in[10];
    const float* b_hh   = (const float*)d_in[11];
    const float* Wg     = (const float*)d_in[12];
    const float* by     = (const float*)d_in[13];
    float* out = (float*)d_out;

    const int smem_bytes = 3*NB*CL2*sizeof(float2);   // 99,840 B -> 2 blocks/SM
    static int configured = 0;
    if (!configured) {
        cudaFuncSetAttribute(fused_kernel,
                             cudaFuncAttributeMaxDynamicSharedMemorySize, smem_bytes);
        configured = 1;
    }

    prep_kernel<<<(Bc*(Tc/4))/256, 256>>>(x, fc1_w, fc1_b, fc2_w, fc2_b);
    fused_kernel<<<CH*NG, NTH, smem_bytes>>>(x, log_pi, log_A, w_ih, w_hh, b_ih, b_hh,
                                             Q_seq, Wg, by, out);
}